// round 17
// baseline (speedup 1.0000x reference)
#include <cuda_runtime.h>
#include <math.h>

#define N_ATOMS  4096
#define NRBF     16
#define NHID     64

#define NCELL1   8                       // cells per axis (BOX/CUTOFF = 40/5)
#define NCELLS   (NCELL1*NCELL1*NCELL1)  // 512
#define ACC_CAP  96                      // accepted per HALF-candidate-set (mean ~17)
#define INV_CELL 0.2f                    // 1 / 5.0
#define GBLK     1024                    // gather blocks (4 atoms each)

// ---- scratch (no allocations allowed) ----
__device__ float4 g_pos_sorted[N_ATOMS + 32];  // cell-major sorted positions (+pad)
__device__ int    g_cell_start[NCELLS + 1];    // prefix offsets into g_pos_sorted
__device__ float  g_block_e[GBLK];             // per-block energy partials
__device__ int    g_done;                      // last-block ticket (reset in build)

// 1/(2*eta^2), eta = 0.5*(5.0-0.5)/16 = 9/64 -> A = 2048/81
#define RBF_A        25.28395061728395f
#define PI_OVER_CUT  0.6283185307179586f       // pi / 5.0
#define CUT_SQ       25.0f

__device__ __forceinline__ int cell_coord(float x)
{
    return min(NCELL1 - 1, max(0, (int)(x * INV_CELL)));
}

// ============================================================
// Kernel 1: stable counting sort of positions by cell.
// 256 blocks x 256 threads, FOUR warps per cell (quarter q scans
// atoms [q*1024, q*1024+1024)). Serial ballot chain = 32 links.
// Deterministic: quarter order preserves index order.
// ============================================================
__global__ __launch_bounds__(256)
void build_kernel(const float* __restrict__ pos)
{
    __shared__ int s_ids[N_ATOMS];   // 16 KB
    __shared__ int s_lt[8], s_eq[8];

    const int tid  = threadIdx.x;
    const int warp = tid >> 5;
    const int lane = tid & 31;
    const unsigned FULL = 0xffffffffu;
    const unsigned ltm  = (1u << lane) - 1u;

    if (blockIdx.x == 0 && tid == 0) {
        g_done = 0;                          // replay-safe ticket reset
        g_cell_start[NCELLS] = N_ATOMS;
    }

    for (int a = tid; a < N_ATOMS; a += 256) {
        float x = pos[3 * a], y = pos[3 * a + 1], z = pos[3 * a + 2];
        s_ids[a] = (cell_coord(z) * NCELL1 + cell_coord(y)) * NCELL1 + cell_coord(x);
    }
    __syncthreads();

    const int cell = blockIdx.x * 2 + (warp >> 2);   // 2 cells per block
    const int q    = warp & 3;                       // quarter
    const int h0   = q * (N_ATOMS / 4);
    const int cg   = warp & ~3;                      // first warp of my cell group

    // pass 1 over own quarter: counts of (id < cell) and (id == cell)
    int lt_cnt = 0, eq_cnt = 0;
    #pragma unroll 4
    for (int b = 0; b < N_ATOMS / 4; b += 32) {
        int id = s_ids[h0 + b + lane];
        lt_cnt += __popc(__ballot_sync(FULL, id < cell));
        eq_cnt += __popc(__ballot_sync(FULL, id == cell));
    }
    if (lane == 0) { s_lt[warp] = lt_cnt; s_eq[warp] = eq_cnt; }
    __syncthreads();

    const int base = s_lt[cg] + s_lt[cg + 1] + s_lt[cg + 2] + s_lt[cg + 3];
    int pref = 0;
    #pragma unroll
    for (int qq = 0; qq < 4; qq++)
        if (qq < q) pref += s_eq[cg + qq];
    const int start = base + pref;                   // stable: lower quarters first
    if (q == 0 && lane == 0) g_cell_start[cell] = base;

    // pass 2: stable scatter of own quarter's matching atoms
    int wpos = start;
    #pragma unroll 4
    for (int b = 0; b < N_ATOMS / 4; b += 32) {
        int  a  = h0 + b + lane;
        bool eq = (s_ids[a] == cell);
        unsigned m = __ballot_sync(FULL, eq);
        if (eq) {
            int dst = wpos + __popc(m & ltm);
            g_pos_sorted[dst] = make_float4(pos[3 * a], pos[3 * a + 1],
                                            pos[3 * a + 2], 0.0f);
        }
        wpos += __popc(m);
    }
}

// ============================================================
__device__ __forceinline__ float silu_f(float a)
{
    return a / (1.0f + __expf(-a));
}

// centers come from shared (frees 16 registers; LDS rides the MUFU loop)
__device__ __forceinline__ void rbf_batch(float sq, const float* __restrict__ sc,
                                          float* __restrict__ f)
{
    float d = sqrtf(sq);                          // sentinel sq=1e8 -> d=1e4
    float w = 0.5f + 0.5f * __cosf(d * PI_OVER_CUT);
    #pragma unroll
    for (int k = 0; k < NRBF; k++) {
        float tt = d - sc[k];
        float g  = __expf(-RBF_A * tt * tt);      // sentinel -> underflow to 0
        f[k] = fmaf(w, g, f[k]);
    }
}

// ============================================================
// Kernel 2: TWO WARPS PER ATOM (parity splits the 9 candidate
// runs). 1024 blocks x 256 threads; __launch_bounds__(256,6)
// pins regs <= 42 -> 6 blocks/SM -> 75% occupancy cap.
// ============================================================
__global__ __launch_bounds__(256, 6)
void gather_kernel(const float* __restrict__ centers,
                   const float* __restrict__ W1, const float* __restrict__ b1,
                   const float* __restrict__ W2, const float* __restrict__ b2,
                   const float* __restrict__ W3, const float* __restrict__ b3,
                   float* __restrict__ out)
{
    __shared__ float s_acc[8][ACC_CAP];                 // 3 KB accepted sq per warp
    __shared__ __align__(16) float s_c[NRBF];           // centers
    __shared__ __align__(16) float s_feat[4][2][NRBF];  // 512 B half-features
    __shared__ __align__(16) float s_h1[4][NHID];       // 1 KB hidden activations
    __shared__ float s_ev[4][2];
    __shared__ float s_e[4];
    __shared__ int   s_last;
    __shared__ float s_red[256];

    const int tid   = threadIdx.x;
    const int warp  = tid >> 5;
    const int lane  = tid & 31;
    const int a_loc = warp >> 1;              // 0..3  (atom within block)
    const int p     = warp & 1;               // candidate-half parity
    const int i     = blockIdx.x * 4 + a_loc; // sorted atom slot
    const unsigned FULL = 0xffffffffu;
    const unsigned ltm  = (1u << lane) - 1u;

    if (tid < NRBF) s_c[tid] = centers[tid];
    __syncthreads();

    const float4 pi = g_pos_sorted[i];        // broadcast, 1 line
    const int cx = cell_coord(pi.x);
    const int cy = cell_coord(pi.y);
    const int cz = cell_coord(pi.z);

    // ---- 9 candidate runs: lanes 0..8 own one (y,z) row each ----
    int rs = 0, rl = 0;
    if (lane < 9) {
        int dz = lane / 3 - 1, dy = lane % 3 - 1;
        int z = cz + dz, y = cy + dy;
        if (z >= 0 && z < NCELL1 && y >= 0 && y < NCELL1) {
            int rowbase = (z * NCELL1 + y) * NCELL1;
            int x0 = max(0, cx - 1), x1 = min(NCELL1 - 1, cx + 1);
            rs = g_cell_start[rowbase + x0];
            rl = g_cell_start[rowbase + x1 + 1] - rs;
        }
    }

    // ---- filter my half of the runs (p=0: 0..4, p=1: 5..8) ----
    const int r0 = p ? 5 : 0;
    const int r1 = p ? 9 : 5;
    int acc = 0;
    for (int r = r0; r < r1; r++) {
        int rs_b = __shfl_sync(FULL, rs, r);
        int rl_b = __shfl_sync(FULL, rl, r);
        for (int b = 0; b < rl_b; b += 32) {
            int k = b + lane;
            float4 pj = (k < rl_b) ? g_pos_sorted[rs_b + k]
                                   : make_float4(pi.x, pi.y, pi.z, 0.0f);
            float dx  = pi.x - pj.x;
            float dy  = pi.y - pj.y;
            float dzv = pi.z - pj.z;
            float sq  = fmaf(dx, dx, fmaf(dy, dy, dzv * dzv));
            bool  ok  = (sq > 0.0f) && (sq < CUT_SQ);   // excludes self exactly
            unsigned m = __ballot_sync(FULL, ok);
            if (ok) {
                int ofs = acc + __popc(m & ltm);
                if (ofs < ACC_CAP) s_acc[warp][ofs] = sq;
            }
            acc += __popc(m);
        }
    }
    acc = min(acc, ACC_CAP);
    __syncwarp();

    // ---- dense RBF over accepted pairs (~1 batch per half) ----
    float f[NRBF];
    #pragma unroll
    for (int k = 0; k < NRBF; k++) f[k] = 0.0f;
    for (int b = 0; b < acc; b += 32) {
        float sqv = (b + lane < acc) ? s_acc[warp][b + lane] : 1e8f;
        rbf_batch(sqv, s_c, f);
    }

    // butterfly-reduce within warp
    #pragma unroll
    for (int off = 16; off > 0; off >>= 1) {
        #pragma unroll
        for (int k = 0; k < NRBF; k++)
            f[k] += __shfl_xor_sync(FULL, f[k], off);
    }

    // ---- combine the two half-feature vectors ----
    if (lane < NRBF) s_feat[a_loc][p][lane] = f[lane];
    __syncthreads();
    #pragma unroll
    for (int k = 0; k < NRBF; k++)
        f[k] += s_feat[a_loc][p ^ 1][k];      // every lane: full features

    // ---- MLP: 1 hidden unit per lane (unit t = p*32 + lane) ----
    const int t = p * 32 + lane;
    float a0 = __ldg(&b1[t]);
    #pragma unroll
    for (int k = 0; k < NRBF; k++)
        a0 = fmaf(f[k], __ldg(&W1[k * NHID + t]), a0);
    s_h1[a_loc][t] = silu_f(a0);
    __syncthreads();

    float a2 = __ldg(&b2[t]);
    #pragma unroll
    for (int u = 0; u < NHID; u += 4) {
        float4 hv = *reinterpret_cast<const float4*>(&s_h1[a_loc][u]);
        a2 = fmaf(hv.x, __ldg(&W2[(u + 0) * NHID + t]), a2);
        a2 = fmaf(hv.y, __ldg(&W2[(u + 1) * NHID + t]), a2);
        a2 = fmaf(hv.z, __ldg(&W2[(u + 2) * NHID + t]), a2);
        a2 = fmaf(hv.w, __ldg(&W2[(u + 3) * NHID + t]), a2);
    }

    float v = silu_f(a2) * __ldg(&W3[t]);
    #pragma unroll
    for (int off = 16; off > 0; off >>= 1)
        v += __shfl_down_sync(FULL, v, off);
    if (lane == 0) s_ev[a_loc][p] = v;
    __syncthreads();

    if (p == 0 && lane == 0)
        s_e[a_loc] = s_ev[a_loc][0] + s_ev[a_loc][1] + __ldg(&b3[0]);
    __syncthreads();

    // ---- block partial + last-block deterministic reduction ----
    if (tid == 0) {
        float be = s_e[0] + s_e[1] + s_e[2] + s_e[3];   // fixed order
        g_block_e[blockIdx.x] = be;
        __threadfence();
        int tk = atomicAdd(&g_done, 1);
        s_last = (tk == gridDim.x - 1);
    }
    __syncthreads();

    if (s_last) {
        float v2 = g_block_e[tid]       + g_block_e[tid + 256]
                 + g_block_e[tid + 512] + g_block_e[tid + 768];  // fixed order
        s_red[tid] = v2;
        __syncthreads();
        #pragma unroll
        for (int s = 128; s > 0; s >>= 1) {
            if (tid < s) s_red[tid] += s_red[tid + s];
            __syncthreads();
        }
        if (tid == 0) out[0] = s_red[0];
    }
}

// ============================================================
extern "C" void kernel_launch(void* const* d_in, const int* in_sizes, int n_in,
                              void* d_out, int out_size)
{
    const float* pos     = (const float*)d_in[0];
    const float* centers = (const float*)d_in[1];
    const float* W1      = (const float*)d_in[2];
    const float* b1      = (const float*)d_in[3];
    const float* W2      = (const float*)d_in[4];
    const float* b2      = (const float*)d_in[5];
    const float* W3      = (const float*)d_in[6];
    const float* b3      = (const float*)d_in[7];

    build_kernel<<<NCELLS / 2, 256>>>(pos);
    gather_kernel<<<GBLK, 256>>>(centers, W1, b1, W2, b2, W3, b3,
                                 (float*)d_out);
}